// round 11
// baseline (speedup 1.0000x reference)
#include <cuda_runtime.h>
#include <cuda_fp16.h>
#include <math.h>
#include <stdint.h>

#define GD     96
#define GS     (GD*GD*GD)
#define CCH    16
#define NPTS   1000000
#define NWARP  12
#define ROWS   16                          // rows (points) per warp
#define TILE   (NWARP*ROWS)                // 192 points per CTA iteration
#define NTILES ((NPTS + TILE - 1) / TILE)

// weight fragments in uint4 units: L0 (K pad 52->64): 4*8*32=1024; hidden: 8*8*32=2048 each
#define W4_L0   0
#define W4_L1   1024
#define W4_TOT  7168

#define ACT_WORDS 36                       // uint words per row (144 B, 16B-aligned)
#define SM_WOUT  (W4_TOT*16)
#define SM_ACT   (SM_WOUT + 512)
#define SMEM_TOTAL (SM_ACT + NWARP*ROWS*ACT_WORDS*4)   // 142848 B

__device__ __align__(16) __half g_grid[GS * CCH];     // [z][y][x][c] fp16
__device__ __align__(16) __half g_wfrag[W4_TOT * 8];  // B-fragment packed weights

__device__ __forceinline__ unsigned packh2(float a, float b) {
  __half2 h = __floats2half2_rn(a, b);
  return *reinterpret_cast<unsigned*>(&h);
}
// relu+pack on the half2 pipe (exact vs fmaxf-then-cvt)
__device__ __forceinline__ unsigned packh2r(float a, float b) {
  __half2 h = __hmax2(__floats2half2_rn(a, b), __float2half2_rn(0.f));
  return *reinterpret_cast<unsigned*>(&h);
}
__device__ __forceinline__ float2 h2f2(unsigned u) {
  __half2 h = *reinterpret_cast<__half2*>(&u);
  return __half22float2(h);
}
__device__ __forceinline__ void mma_acc(float* d, const unsigned* a, unsigned b0, unsigned b1) {
  asm("mma.sync.aligned.m16n8k16.row.col.f32.f16.f16.f32 "
      "{%0,%1,%2,%3}, {%4,%5,%6,%7}, {%8,%9}, {%0,%1,%2,%3};\n"
      : "+f"(d[0]), "+f"(d[1]), "+f"(d[2]), "+f"(d[3])
      : "r"(a[0]), "r"(a[1]), "r"(a[2]), "r"(a[3]), "r"(b0), "r"(b1));
}
__device__ __forceinline__ void mma_zero(float* d, const unsigned* a, unsigned b0, unsigned b1) {
  asm("mma.sync.aligned.m16n8k16.row.col.f32.f16.f16.f32 "
      "{%0,%1,%2,%3}, {%4,%5,%6,%7}, {%8,%9}, {%10,%10,%10,%10};\n"
      : "=f"(d[0]), "=f"(d[1]), "=f"(d[2]), "=f"(d[3])
      : "r"(a[0]), "r"(a[1]), "r"(a[2]), "r"(a[3]), "r"(b0), "r"(b1), "f"(0.f));
}

// ---- prep (one kernel): grid transpose + weight B-fragment packing ----
__global__ void k_prep(const float* __restrict__ fg, const float* __restrict__ wi,
                       const float* __restrict__ h0, const float* __restrict__ h1,
                       const float* __restrict__ h2) {
  int b = blockIdx.x;
  if (b < 3456) {                      // [C,D,H,W] f32 -> [D,H,W,C] f16
    int s = b * 256 + threadIdx.x;
    if (s >= GS) return;
    unsigned u[8];
    #pragma unroll
    for (int c = 0; c < 8; c++)
      u[c] = packh2(fg[(2*c)*GS + s], fg[(2*c+1)*GS + s]);
    uint4* dst = (uint4*)(g_grid + s*CCH);
    dst[0] = make_uint4(u[0], u[1], u[2], u[3]);
    dst[1] = make_uint4(u[4], u[5], u[6], u[7]);
  } else {
    int tid = (b - 3456) * 256 + threadIdx.x;
    if (tid >= W4_TOT) return;
    const float* W; int K; int rem;
    if (tid < W4_L1) { W = wi; K = 52; rem = tid; }
    else {
      int u = tid - W4_L1;
      int layer = u >> 11;
      rem = u & 2047;
      W = (layer == 0) ? h0 : (layer == 1) ? h1 : h2;
      K = 128;
    }
    int lane = rem & 31, p = (rem >> 5) & 7, kt = rem >> 8;
    int g = lane >> 2, t = lane & 3;
    int k0 = kt*16 + 2*t, n0 = p*16 + g;
    float v[8];
    #pragma unroll
    for (int q = 0; q < 8; q++) {
      int k = k0 + ((q >> 1) & 1)*8 + (q & 1);
      int n = n0 + (q >> 2)*8;
      v[q] = (k < K) ? W[k*128 + n] : 0.f;
    }
    *(uint4*)(g_wfrag + tid*8) =
        make_uint4(packh2(v[0],v[1]), packh2(v[2],v[3]), packh2(v[4],v[5]), packh2(v[6],v[7]));
  }
}

// ---- main: 12 warps x 16 rows (3 warps/SMSP), serial FE -> chain, 2-deep B pipe ----
__global__ __launch_bounds__(384, 1)
void k_mlp(const float* __restrict__ xin, const float* __restrict__ w_out,
           float* __restrict__ out) {
  extern __shared__ unsigned char smem[];
  uint4*  wsm     = (uint4*)smem;
  float*  wout_sm = (float*)(smem + SM_WOUT);

  for (int k = threadIdx.x; k < W4_TOT; k += 384) wsm[k] = ((const uint4*)g_wfrag)[k];
  if (threadIdx.x < 128) wout_sm[threadIdx.x] = w_out[threadIdx.x];
  __syncthreads();

  const int warp = threadIdx.x >> 5, lane = threadIdx.x & 31;
  const int g = lane >> 2, t = lane & 3;
  const int pl = lane & 15;            // point slot (lanes 16-31 mirror 0-15 in FE)
  unsigned* mybuf = (unsigned*)(smem + SM_ACT) + warp*ROWS*ACT_WORDS;

  // rolling x coords for the next tile
  float px = 0.f, py = 0.f, pz = 0.f;
  {
    int i = blockIdx.x * TILE + warp * ROWS + pl;
    if (i < NPTS) { px = xin[3*i]; py = xin[3*i+1]; pz = xin[3*i+2]; }
  }

  for (int tile = blockIdx.x; tile < NTILES; tile += gridDim.x) {
    const int base = tile * TILE + warp * ROWS;

    // ================= front end (half-warp mirrored) =================
    float fx = (px + 1.f) * 47.5f, fy = (py + 1.f) * 47.5f, fz = (pz + 1.f) * 47.5f;
    float xf = floorf(fx), yf = floorf(fy), zf = floorf(fz);
    float tx = fx - xf, ty = fy - yf, tz = fz - zf;
    int x0 = min(max((int)xf, 0), GD-1), x1 = min(x0+1, GD-1);
    int y0 = min(max((int)yf, 0), GD-1), y1 = min(y0+1, GD-1);
    int z0 = min(max((int)zf, 0), GD-1), z1 = min(z0+1, GD-1);
    int bz0 = z0*(GD*GD*CCH), bz1 = z1*(GD*GD*CCH);
    int by0 = y0*(GD*CCH),    by1 = y1*(GD*CCH);
    int bx0 = x0*CCH,         bx1 = x1*CCH;
    int ad[8] = { bz0+by0+bx0, bz0+by0+bx1, bz0+by1+bx0, bz0+by1+bx1,
                  bz1+by0+bx0, bz1+by0+bx1, bz1+by1+bx0, bz1+by1+bx1 };
    uint4 q[16];
    #pragma unroll
    for (int c = 0; c < 8; c++) {
      q[2*c]   = *(const uint4*)(g_grid + ad[c]);
      q[2*c+1] = *(const uint4*)(g_grid + ad[c] + 8);
    }
    float opx = px, opy = py, opz = pz;
    {   // prefetch next tile's x (in flight through the whole chain)
      int tn = tile + gridDim.x;
      int j = tn * TILE + warp * ROWS + pl;
      float ax = 0.f, ay = 0.f, az = 0.f;
      if (tn < NTILES && j < NPTS) { ax = xin[3*j]; ay = xin[3*j+1]; az = xin[3*j+2]; }
      px = ax; py = ay; pz = az;
    }
    unsigned in[32];
    {   // pos-enc while gathers fly (levels 0-2 SFU, 3-5 double-angle)
      const float PI = 3.14159265358979323846f;
      float sx, cx, sy, cy, sz, cz, fr = PI;
      #pragma unroll
      for (int l = 0; l < 3; l++) {
        __sincosf(opx*fr, &sx, &cx);
        __sincosf(opy*fr, &sy, &cy);
        __sincosf(opz*fr, &sz, &cz);
        in[l*3+0] = packh2(sx,sy); in[l*3+1] = packh2(sz,cx); in[l*3+2] = packh2(cy,cz);
        fr *= 2.f;
      }
      #pragma unroll
      for (int l = 3; l < 6; l++) {
        float a2 = 2.f*sx*cx, b2 = 1.f - 2.f*sx*sx; sx = a2; cx = b2;
        a2 = 2.f*sy*cy; b2 = 1.f - 2.f*sy*sy; sy = a2; cy = b2;
        a2 = 2.f*sz*cz; b2 = 1.f - 2.f*sz*sz; sz = a2; cz = b2;
        in[l*3+0] = packh2(sx,sy); in[l*3+1] = packh2(sz,cx); in[l*3+2] = packh2(cy,cz);
      }
    }
    {   // trilerp (consume gathers)
      float wx0 = 1.f-tx, wy0 = 1.f-ty, wz0 = 1.f-tz;
      float cw[8] = { wz0*wy0*wx0, wz0*wy0*tx, wz0*ty*wx0, wz0*ty*tx,
                      tz*wy0*wx0,  tz*wy0*tx,  tz*ty*wx0,  tz*ty*tx };
      float f[16];
      #pragma unroll
      for (int c = 0; c < 16; c++) f[c] = 0.f;
      #pragma unroll
      for (int c = 0; c < 8; c++) {
        float wc = cw[c];
        const unsigned* qa = (const unsigned*)&q[2*c];
        #pragma unroll
        for (int j = 0; j < 8; j++) {
          float2 v = h2f2(qa[j]);
          f[2*j] += wc*v.x; f[2*j+1] += wc*v.y;
        }
      }
      #pragma unroll
      for (int c = 0; c < 8; c++) in[18+c] = packh2(f[2*c], f[2*c+1]);
      #pragma unroll
      for (int c = 26; c < 32; c++) in[c] = 0u;
    }
    if (lane < 16) {   // stage rows: 8x STS.128, one writer per row
      uint4* rp = (uint4*)(mybuf + pl*ACT_WORDS);
      #pragma unroll
      for (int c = 0; c < 8; c++)
        rp[c] = make_uint4(in[4*c], in[4*c+1], in[4*c+2], in[4*c+3]);
    }
    __syncwarp();

    // ================= layer 0: K=64, 2-deep B pipeline =================
    unsigned a0[4][4];
    #pragma unroll
    for (int kt = 0; kt < 4; kt++) {
      const unsigned* r0 = mybuf + (g  )*ACT_WORDS + (kt*8 + t);
      const unsigned* r1 = mybuf + (g+8)*ACT_WORDS + (kt*8 + t);
      a0[kt][0] = r0[0]; a0[kt][1] = r1[0];
      a0[kt][2] = r0[4]; a0[kt][3] = r1[4];
    }
    float acc[16][4];
    {
      uint4 b0 = wsm[W4_L0 + lane];
      uint4 b1 = wsm[W4_L0 + 32 + lane];
      #pragma unroll
      for (int it = 0; it < 32; it++) {
        uint4 b2;
        if (it < 30) b2 = wsm[W4_L0 + (it+2)*32 + lane];
        int kt = it >> 3, p = it & 7;
        if (kt == 0) { mma_zero(acc[2*p],   a0[kt], b0.x, b0.y);
                       mma_zero(acc[2*p+1], a0[kt], b0.z, b0.w); }
        else         { mma_acc (acc[2*p],   a0[kt], b0.x, b0.y);
                       mma_acc (acc[2*p+1], a0[kt], b0.z, b0.w); }
        b0 = b1;
        if (it < 30) b1 = b2;
      }
    }

    // ================= hidden layers: C -> relu-pack -> A in regs =================
    #pragma unroll
    for (int layer = 0; layer < 3; layer++) {
      const uint4* wb = wsm + W4_L1 + layer*2048;
      uint4 b0 = wb[lane];
      uint4 b1 = wb[32 + lane];
      unsigned af[8][4];
      #pragma unroll
      for (int kt = 0; kt < 8; kt++) {
        af[kt][0] = packh2r(acc[2*kt  ][0], acc[2*kt  ][1]);
        af[kt][1] = packh2r(acc[2*kt  ][2], acc[2*kt  ][3]);
        af[kt][2] = packh2r(acc[2*kt+1][0], acc[2*kt+1][1]);
        af[kt][3] = packh2r(acc[2*kt+1][2], acc[2*kt+1][3]);
      }
      #pragma unroll
      for (int it = 0; it < 64; it++) {
        uint4 b2;
        if (it < 62) b2 = wb[(it+2)*32 + lane];
        int kt = it >> 3, p = it & 7;
        if (kt == 0) { mma_zero(acc[2*p],   af[kt], b0.x, b0.y);
                       mma_zero(acc[2*p+1], af[kt], b0.z, b0.w); }
        else         { mma_acc (acc[2*p],   af[kt], b0.x, b0.y);
                       mma_acc (acc[2*p+1], af[kt], b0.z, b0.w); }
        b0 = b1;
        if (it < 62) b1 = b2;
      }
    }

    // ================= output: relu(acc) . w_out, quad reduce =================
    {
      float y0 = 0.f, y1 = 0.f;
      #pragma unroll
      for (int nt = 0; nt < 16; nt++) {
        float w0 = wout_sm[nt*8 + 2*t], w1 = wout_sm[nt*8 + 2*t + 1];
        y0 += fmaxf(acc[nt][0],0.f)*w0 + fmaxf(acc[nt][1],0.f)*w1;
        y1 += fmaxf(acc[nt][2],0.f)*w0 + fmaxf(acc[nt][3],0.f)*w1;
      }
      y0 += __shfl_xor_sync(0xFFFFFFFFu, y0, 1); y0 += __shfl_xor_sync(0xFFFFFFFFu, y0, 2);
      y1 += __shfl_xor_sync(0xFFFFFFFFu, y1, 1); y1 += __shfl_xor_sync(0xFFFFFFFFu, y1, 2);
      if (t == 0) {
        int i0 = base + g;
        if (i0     < NPTS) out[i0]     = y0;
        if (i0 + 8 < NPTS) out[i0 + 8] = y1;
      }
    }
    __syncwarp();
  }
}

extern "C" void kernel_launch(void* const* d_in, const int* in_sizes, int n_in,
                              void* d_out, int out_size) {
  const float* x  = (const float*)d_in[0];
  const float* fg = (const float*)d_in[1];
  const float* wi = (const float*)d_in[2];
  const float* h0 = (const float*)d_in[3];
  const float* h1 = (const float*)d_in[4];
  const float* h2 = (const float*)d_in[5];
  const float* wo = (const float*)d_in[6];
  float* out = (float*)d_out;

  cudaFuncSetAttribute(k_mlp, cudaFuncAttributeMaxDynamicSharedMemorySize, SMEM_TOTAL);
  int dev = 0, sms = 148;
  cudaGetDevice(&dev);
  cudaDeviceGetAttribute(&sms, cudaDevAttrMultiProcessorCount, dev);

  k_prep<<<3456 + (W4_TOT + 255)/256, 256>>>(fg, wi, h0, h1, h2);
  k_mlp<<<sms, 384, SMEM_TOTAL>>>(x, wo, out);
}

// round 12
// speedup vs baseline: 1.1975x; 1.1975x over previous
#include <cuda_runtime.h>
#include <cuda_fp16.h>
#include <math.h>
#include <stdint.h>

#define GD     96
#define GS     (GD*GD*GD)
#define CCH    16
#define NPTS   1000000
#define TILE   256
#define NTILES ((NPTS + TILE - 1) / TILE)

// weight fragments in uint4 units: L0 (K pad 52->64): 4*8*32=1024; hidden: 8*8*32=2048 each
#define W4_L0   0
#define W4_L1   1024
#define W4_TOT  7168

#define ACT_WORDS 36                       // uint words per row (144 B, 16B-aligned)
#define SM_WOUT  (W4_TOT*16)
#define SM_ACT   (SM_WOUT + 512)
#define SMEM_TOTAL (SM_ACT + 8*32*ACT_WORDS*4)   // 152064 B
// NOTE: 4-deep ring reloads read up to 127 uint4 past a layer's weight region.
// Max smem read index: (5120 + 67*32 + 31)*16 = 116720 B < SMEM_TOTAL. The
// over-read values are never consumed (ring slot dies before use). Safe.

__device__ __align__(16) __half g_grid[GS * CCH];     // [z][y][x][c] fp16
__device__ __align__(16) __half g_wfrag[W4_TOT * 8];  // B-fragment packed weights

__device__ __forceinline__ unsigned packh2(float a, float b) {
  __half2 h = __floats2half2_rn(a, b);
  return *reinterpret_cast<unsigned*>(&h);
}
// relu+pack on the half2 pipe (exact vs fmaxf-then-cvt)
__device__ __forceinline__ unsigned packh2r(float a, float b) {
  __half2 h = __hmax2(__floats2half2_rn(a, b), __float2half2_rn(0.f));
  return *reinterpret_cast<unsigned*>(&h);
}
__device__ __forceinline__ float2 h2f2(unsigned u) {
  __half2 h = *reinterpret_cast<__half2*>(&u);
  return __half22float2(h);
}
__device__ __forceinline__ void mma_acc(float* d, const unsigned* a, unsigned b0, unsigned b1) {
  asm("mma.sync.aligned.m16n8k16.row.col.f32.f16.f16.f32 "
      "{%0,%1,%2,%3}, {%4,%5,%6,%7}, {%8,%9}, {%0,%1,%2,%3};\n"
      : "+f"(d[0]), "+f"(d[1]), "+f"(d[2]), "+f"(d[3])
      : "r"(a[0]), "r"(a[1]), "r"(a[2]), "r"(a[3]), "r"(b0), "r"(b1));
}
__device__ __forceinline__ void mma_zero(float* d, const unsigned* a, unsigned b0, unsigned b1) {
  asm("mma.sync.aligned.m16n8k16.row.col.f32.f16.f16.f32 "
      "{%0,%1,%2,%3}, {%4,%5,%6,%7}, {%8,%9}, {%10,%10,%10,%10};\n"
      : "=f"(d[0]), "=f"(d[1]), "=f"(d[2]), "=f"(d[3])
      : "r"(a[0]), "r"(a[1]), "r"(a[2]), "r"(a[3]), "r"(b0), "r"(b1), "f"(0.f));
}

// ---- prep (one kernel): grid transpose + weight B-fragment packing ----
__global__ void k_prep(const float* __restrict__ fg, const float* __restrict__ wi,
                       const float* __restrict__ h0, const float* __restrict__ h1,
                       const float* __restrict__ h2) {
  int b = blockIdx.x;
  if (b < 3456) {                      // [C,D,H,W] f32 -> [D,H,W,C] f16
    int s = b * 256 + threadIdx.x;
    if (s >= GS) return;
    unsigned u[8];
    #pragma unroll
    for (int c = 0; c < 8; c++)
      u[c] = packh2(fg[(2*c)*GS + s], fg[(2*c+1)*GS + s]);
    uint4* dst = (uint4*)(g_grid + s*CCH);
    dst[0] = make_uint4(u[0], u[1], u[2], u[3]);
    dst[1] = make_uint4(u[4], u[5], u[6], u[7]);
  } else {
    int tid = (b - 3456) * 256 + threadIdx.x;
    if (tid >= W4_TOT) return;
    const float* W; int K; int rem;
    if (tid < W4_L1) { W = wi; K = 52; rem = tid; }
    else {
      int u = tid - W4_L1;
      int layer = u >> 11;
      rem = u & 2047;
      W = (layer == 0) ? h0 : (layer == 1) ? h1 : h2;
      K = 128;
    }
    int lane = rem & 31, p = (rem >> 5) & 7, kt = rem >> 8;
    int g = lane >> 2, t = lane & 3;
    int k0 = kt*16 + 2*t, n0 = p*16 + g;
    float v[8];
    #pragma unroll
    for (int q = 0; q < 8; q++) {
      int k = k0 + ((q >> 1) & 1)*8 + (q & 1);
      int n = n0 + (q >> 2)*8;
      v[q] = (k < K) ? W[k*128 + n] : 0.f;
    }
    *(uint4*)(g_wfrag + tid*8) =
        make_uint4(packh2(v[0],v[1]), packh2(v[2],v[3]), packh2(v[4],v[5]), packh2(v[6],v[7]));
  }
}

// ---- main: persistent CTAs, 8 warps x 32 rows, serial FE -> chain, 4-deep B ring ----
__global__ __launch_bounds__(256, 1)
void k_mlp(const float* __restrict__ xin, const float* __restrict__ w_out,
           float* __restrict__ out) {
  extern __shared__ unsigned char smem[];
  uint4*  wsm     = (uint4*)smem;
  float*  wout_sm = (float*)(smem + SM_WOUT);

  for (int k = threadIdx.x; k < W4_TOT; k += 256) wsm[k] = ((const uint4*)g_wfrag)[k];
  if (threadIdx.x < 128) wout_sm[threadIdx.x] = w_out[threadIdx.x];
  __syncthreads();

  const int warp = threadIdx.x >> 5, lane = threadIdx.x & 31;
  const int g = lane >> 2, t = lane & 3;
  unsigned* mybuf = (unsigned*)(smem + SM_ACT) + warp*32*ACT_WORDS;

  // rolling x coords for the next tile
  float px = 0.f, py = 0.f, pz = 0.f;
  {
    int i = blockIdx.x * TILE + warp * 32 + lane;
    if (i < NPTS) { px = xin[3*i]; py = xin[3*i+1]; pz = xin[3*i+2]; }
  }

  for (int tile = blockIdx.x; tile < NTILES; tile += gridDim.x) {
    const int base = tile * TILE + warp * 32;

    // ================= front end =================
    float fx = (px + 1.f) * 47.5f, fy = (py + 1.f) * 47.5f, fz = (pz + 1.f) * 47.5f;
    float xf = floorf(fx), yf = floorf(fy), zf = floorf(fz);
    float tx = fx - xf, ty = fy - yf, tz = fz - zf;
    int x0 = min(max((int)xf, 0), GD-1), x1 = min(x0+1, GD-1);
    int y0 = min(max((int)yf, 0), GD-1), y1 = min(y0+1, GD-1);
    int z0 = min(max((int)zf, 0), GD-1), z1 = min(z0+1, GD-1);
    int bz0 = z0*(GD*GD*CCH), bz1 = z1*(GD*GD*CCH);
    int by0 = y0*(GD*CCH),    by1 = y1*(GD*CCH);
    int bx0 = x0*CCH,         bx1 = x1*CCH;
    int ad[8] = { bz0+by0+bx0, bz0+by0+bx1, bz0+by1+bx0, bz0+by1+bx1,
                  bz1+by0+bx0, bz1+by0+bx1, bz1+by1+bx0, bz1+by1+bx1 };
    uint4 q[16];
    #pragma unroll
    for (int c = 0; c < 8; c++) {
      q[2*c]   = *(const uint4*)(g_grid + ad[c]);
      q[2*c+1] = *(const uint4*)(g_grid + ad[c] + 8);
    }
    float opx = px, opy = py, opz = pz;
    {   // prefetch next tile's x (in flight through the whole chain)
      int tn = tile + gridDim.x;
      int j = tn * TILE + warp * 32 + lane;
      float ax = 0.f, ay = 0.f, az = 0.f;
      if (tn < NTILES && j < NPTS) { ax = xin[3*j]; ay = xin[3*j+1]; az = xin[3*j+2]; }
      px = ax; py = ay; pz = az;
    }
    unsigned in[32];
    {   // pos-enc while gathers fly (levels 0-2 SFU, 3-5 double-angle)
      const float PI = 3.14159265358979323846f;
      float sx, cx, sy, cy, sz, cz, fr = PI;
      #pragma unroll
      for (int l = 0; l < 3; l++) {
        __sincosf(opx*fr, &sx, &cx);
        __sincosf(opy*fr, &sy, &cy);
        __sincosf(opz*fr, &sz, &cz);
        in[l*3+0] = packh2(sx,sy); in[l*3+1] = packh2(sz,cx); in[l*3+2] = packh2(cy,cz);
        fr *= 2.f;
      }
      #pragma unroll
      for (int l = 3; l < 6; l++) {
        float a2 = 2.f*sx*cx, b2 = 1.f - 2.f*sx*sx; sx = a2; cx = b2;
        a2 = 2.f*sy*cy; b2 = 1.f - 2.f*sy*sy; sy = a2; cy = b2;
        a2 = 2.f*sz*cz; b2 = 1.f - 2.f*sz*sz; sz = a2; cz = b2;
        in[l*3+0] = packh2(sx,sy); in[l*3+1] = packh2(sz,cx); in[l*3+2] = packh2(cy,cz);
      }
    }
    {   // trilerp (consume gathers)
      float wx0 = 1.f-tx, wy0 = 1.f-ty, wz0 = 1.f-tz;
      float cw[8] = { wz0*wy0*wx0, wz0*wy0*tx, wz0*ty*wx0, wz0*ty*tx,
                      tz*wy0*wx0,  tz*wy0*tx,  tz*ty*wx0,  tz*ty*tx };
      float f[16];
      #pragma unroll
      for (int c = 0; c < 16; c++) f[c] = 0.f;
      #pragma unroll
      for (int c = 0; c < 8; c++) {
        float wc = cw[c];
        const unsigned* qa = (const unsigned*)&q[2*c];
        #pragma unroll
        for (int j = 0; j < 8; j++) {
          float2 v = h2f2(qa[j]);
          f[2*j] += wc*v.x; f[2*j+1] += wc*v.y;
        }
      }
      #pragma unroll
      for (int c = 0; c < 8; c++) in[18+c] = packh2(f[2*c], f[2*c+1]);
      #pragma unroll
      for (int c = 26; c < 32; c++) in[c] = 0u;
    }
    {   // stage rows: 8x STS.128 (144B stride, conflict-free)
      uint4* rp = (uint4*)(mybuf + lane*ACT_WORDS);
      #pragma unroll
      for (int c = 0; c < 8; c++)
        rp[c] = make_uint4(in[4*c], in[4*c+1], in[4*c+2], in[4*c+3]);
    }
    __syncwarp();

    // ================= layer 0: K=64, 4-deep B ring =================
    unsigned a0[2][4][4];
    #pragma unroll
    for (int mt = 0; mt < 2; mt++)
      #pragma unroll
      for (int kt = 0; kt < 4; kt++) {
        const unsigned* r0 = mybuf + (mt*16+g  )*ACT_WORDS + (kt*8 + t);
        const unsigned* r1 = mybuf + (mt*16+g+8)*ACT_WORDS + (kt*8 + t);
        a0[mt][kt][0] = r0[0]; a0[mt][kt][1] = r1[0];
        a0[mt][kt][2] = r0[4]; a0[mt][kt][3] = r1[4];
      }
    float acc[2][16][4];
    {
      uint4 br[4];
      #pragma unroll
      for (int i = 0; i < 4; i++) br[i] = wsm[W4_L0 + i*32 + lane];
      #pragma unroll
      for (int it = 0; it < 32; it++) {
        int kt = it >> 3, p = it & 7;
        uint4 b = br[it & 3];
        // unconditional distance-4 reload (over-read harmless, value unused)
        br[it & 3] = wsm[W4_L0 + (it+4)*32 + lane];
        #pragma unroll
        for (int mt = 0; mt < 2; mt++) {
          if (kt == 0) { mma_zero(acc[mt][2*p],   a0[mt][kt], b.x, b.y);
                         mma_zero(acc[mt][2*p+1], a0[mt][kt], b.z, b.w); }
          else         { mma_acc (acc[mt][2*p],   a0[mt][kt], b.x, b.y);
                         mma_acc (acc[mt][2*p+1], a0[mt][kt], b.z, b.w); }
        }
      }
    }

    // ================= hidden layers: C -> relu-pack -> A in regs =================
    #pragma unroll
    for (int layer = 0; layer < 3; layer++) {
      const uint4* wb = wsm + W4_L1 + layer*2048;
      uint4 br[4];
      #pragma unroll
      for (int i = 0; i < 4; i++) br[i] = wb[i*32 + lane];   // refill hidden under pack
      unsigned af[2][8][4];
      #pragma unroll
      for (int mt = 0; mt < 2; mt++)
        #pragma unroll
        for (int kt = 0; kt < 8; kt++) {
          af[mt][kt][0] = packh2r(acc[mt][2*kt  ][0], acc[mt][2*kt  ][1]);
          af[mt][kt][1] = packh2r(acc[mt][2*kt  ][2], acc[mt][2*kt  ][3]);
          af[mt][kt][2] = packh2r(acc[mt][2*kt+1][0], acc[mt][2*kt+1][1]);
          af[mt][kt][3] = packh2r(acc[mt][2*kt+1][2], acc[mt][2*kt+1][3]);
        }
      #pragma unroll
      for (int it = 0; it < 64; it++) {
        int kt = it >> 3, p = it & 7;
        uint4 b = br[it & 3];
        br[it & 3] = wb[(it+4)*32 + lane];   // unconditional, over-read harmless
        #pragma unroll
        for (int mt = 0; mt < 2; mt++) {
          if (kt == 0) { mma_zero(acc[mt][2*p],   af[mt][kt], b.x, b.y);
                         mma_zero(acc[mt][2*p+1], af[mt][kt], b.z, b.w); }
          else         { mma_acc (acc[mt][2*p],   af[mt][kt], b.x, b.y);
                         mma_acc (acc[mt][2*p+1], af[mt][kt], b.z, b.w); }
        }
      }
    }

    // ================= output: relu(acc) . w_out, quad reduce =================
    #pragma unroll
    for (int mt = 0; mt < 2; mt++) {
      float y0 = 0.f, y1 = 0.f;
      #pragma unroll
      for (int nt = 0; nt < 16; nt++) {
        float w0 = wout_sm[nt*8 + 2*t], w1 = wout_sm[nt*8 + 2*t + 1];
        y0 += fmaxf(acc[mt][nt][0],0.f)*w0 + fmaxf(acc[mt][nt][1],0.f)*w1;
        y1 += fmaxf(acc[mt][nt][2],0.f)*w0 + fmaxf(acc[mt][nt][3],0.f)*w1;
      }
      y0 += __shfl_xor_sync(0xFFFFFFFFu, y0, 1); y0 += __shfl_xor_sync(0xFFFFFFFFu, y0, 2);
      y1 += __shfl_xor_sync(0xFFFFFFFFu, y1, 1); y1 += __shfl_xor_sync(0xFFFFFFFFu, y1, 2);
      if (t == 0) {
        int i0 = base + mt*16 + g;
        if (i0     < NPTS) out[i0]     = y0;
        if (i0 + 8 < NPTS) out[i0 + 8] = y1;
      }
    }
    __syncwarp();
  }
}

extern "C" void kernel_launch(void* const* d_in, const int* in_sizes, int n_in,
                              void* d_out, int out_size) {
  const float* x  = (const float*)d_in[0];
  const float* fg = (const float*)d_in[1];
  const float* wi = (const float*)d_in[2];
  const float* h0 = (const float*)d_in[3];
  const float* h1 = (const float*)d_in[4];
  const float* h2 = (const float*)d_in[5];
  const float* wo = (const float*)d_in[6];
  float* out = (float*)d_out;

  cudaFuncSetAttribute(k_mlp, cudaFuncAttributeMaxDynamicSharedMemorySize, SMEM_TOTAL);
  int dev = 0, sms = 148;
  cudaGetDevice(&dev);
  cudaDeviceGetAttribute(&sms, cudaDevAttrMultiProcessorCount, dev);

  k_prep<<<3456 + (W4_TOT + 255)/256, 256>>>(fg, wi, h0, h1, h2);
  k_mlp<<<sms, 256, SMEM_TOTAL>>>(x, wo, out);
}